// round 13
// baseline (speedup 1.0000x reference)
#include <cuda_runtime.h>
#include <cuda_bf16.h>
#include <cstdint>

// NetG: encoder GRU -> +noise -> decoder GRU -> FC head.
// mma.sync.m16n8k16 bf16 x3-split GEMM (R10 engine, compute byte-identical).
// R13: group = 8-CTA cluster; sync via SMEM mbarriers (DSMEM arrives +
// local HW-sleep waits) instead of L2 counter+poll; cp.async staging with
// head-reduce overlapped. Entry __syncthreads removed (per-thread wait).

#define TSZ 256
#define HSZ 256
#define BSZ 512
#define NCTA 128
#define NTHR 256

// smem byte offsets
#define A_HI 0                // 32 x 512B swizzled bf16 (Ah)
#define A_LO 16384            // Al
#define CBUF 32768            // float [m stride 404][kw stride 100][n 96]
#define WIHB 84480            // 96 x float4 {w0,w1,w2,bih}
#define BHHO 86016            // 96 floats bhh
#define WFCO 86400            // 96 floats wfc (3 x 32)
#define MBAR 86784            // 8B mbarrier
#define SMEM_BYTES 86800

__device__ __nv_bfloat16 g_hbf[2][2][BSZ * HSZ];  // [hi/lo][buf][b*256+j]
__device__ float g_yp[2][NCTA][32][4];            // head partials

__device__ __forceinline__ uint32_t smem_u32(const void* p) {
    uint32_t a;
    asm("{ .reg .u64 t; cvta.to.shared.u64 t, %1; cvt.u32.u64 %0, t; }"
        : "=r"(a) : "l"(p));
    return a;
}
__device__ __forceinline__ void ldm4(uint32_t* r, uint32_t addr) {
    asm volatile("ldmatrix.sync.aligned.m8n8.x4.shared.b16 {%0,%1,%2,%3}, [%4];"
        : "=r"(r[0]), "=r"(r[1]), "=r"(r[2]), "=r"(r[3]) : "r"(addr));
}
__device__ __forceinline__ void mma16816(float* c, const uint32_t* a,
                                         uint32_t b0, uint32_t b1) {
    asm volatile(
        "mma.sync.aligned.m16n8k16.row.col.f32.bf16.bf16.f32 "
        "{%0,%1,%2,%3}, {%4,%5,%6,%7}, {%8,%9}, {%0,%1,%2,%3};"
        : "+f"(c[0]), "+f"(c[1]), "+f"(c[2]), "+f"(c[3])
        : "r"(a[0]), "r"(a[1]), "r"(a[2]), "r"(a[3]), "r"(b0), "r"(b1));
}
__device__ __forceinline__ void cp16(uint32_t dsts, const void* gsrc) {
    asm volatile("cp.async.cg.shared.global [%0], [%1], 16;"
                 :: "r"(dsts), "l"(gsrc) : "memory");
}
// arrive (release, cluster scope) on the mbarrier at this SMEM offset in CTA r
__device__ __forceinline__ void mbar_arrive_rank(uint32_t mbar, int r) {
    asm volatile(
        "{\n\t.reg .b32 rem;\n\t"
        "mapa.shared::cluster.u32 rem, %0, %1;\n\t"
        "mbarrier.arrive.release.cluster.shared::cluster.b64 _, [rem];\n\t}"
        :: "r"(mbar), "r"(r) : "memory");
}
// HW-sleep wait on local mbarrier phase parity (acquire, cluster scope)
__device__ __forceinline__ void mbar_wait(uint32_t mbar, unsigned parity) {
    asm volatile(
        "{\n\t.reg .pred P;\n\t"
        "WL_%=:\n\t"
        "mbarrier.try_wait.parity.acquire.cluster.shared::cta.b64 P, [%0], %1, 0x989680;\n\t"
        "@P bra.uni WD_%=;\n\t"
        "bra.uni WL_%=;\n\t"
        "WD_%=:\n\t}"
        :: "r"(mbar), "r"(parity) : "memory");
}
__device__ __forceinline__ float sigf(float x) {
    return __fdividef(1.0f, 1.0f + __expf(-x));
}
__device__ __forceinline__ float tanhf_(float x) {
    return 1.0f - __fdividef(2.0f, __expf(2.0f * x) + 1.0f);
}

// Build this warp's B fragments (weights) in registers, split hi/lo bf16.
// Warp covers n-rows [nw*48, nw*48+48), k-quarter [kw*64, kw*64+64).
__device__ __forceinline__ void stage_Bregs(
    const float* __restrict__ W, uint32_t Bh[6][4][2], uint32_t Bl[6][4][2],
    int ib, int nw, int kw, int lane)
{
    const int nr = lane >> 2, kc = (lane & 3) * 2;
    #pragma unroll
    for (int nt = 0; nt < 6; ++nt) {
        int n = nw * 48 + nt * 8 + nr;
        int g = n >> 5, c = n & 31;
        const float* row = W + (g * HSZ + ib * 32 + c) * HSZ;
        #pragma unroll
        for (int kt = 0; kt < 4; ++kt) {
            #pragma unroll
            for (int rg = 0; rg < 2; ++rg) {
                int kk = kw * 64 + kt * 16 + rg * 8 + kc;
                float2 w = *(const float2*)(row + kk);
                __nv_bfloat16 h0 = __float2bfloat16(w.x);
                __nv_bfloat16 h1 = __float2bfloat16(w.y);
                __nv_bfloat16 l0 = __float2bfloat16(w.x - __bfloat162float(h0));
                __nv_bfloat16 l1 = __float2bfloat16(w.y - __bfloat162float(h1));
                Bh[nt][kt][rg] = (uint32_t)__bfloat16_as_ushort(h0)
                               | ((uint32_t)__bfloat16_as_ushort(h1) << 16);
                Bl[nt][kt][rg] = (uint32_t)__bfloat16_as_ushort(l0)
                               | ((uint32_t)__bfloat16_as_ushort(l1) << 16);
            }
        }
    }
}

extern "C" __global__ void __launch_bounds__(NTHR, 1) __cluster_dims__(8, 1, 1)
netg_mma(const float* __restrict__ X_p, const float* __restrict__ X_f,
         const float* __restrict__ noise,
         const float* __restrict__ Wih_e, const float* __restrict__ Whh_e,
         const float* __restrict__ bih_e, const float* __restrict__ bhh_e,
         const float* __restrict__ Wih_d, const float* __restrict__ Whh_d,
         const float* __restrict__ bih_d, const float* __restrict__ bhh_d,
         const float* __restrict__ Wfc,   const float* __restrict__ bfc,
         float* __restrict__ out)
{
    extern __shared__ char smc[];
    const uint32_t smb = smem_u32(smc);
    const int tid = threadIdx.x, lane = tid & 31, wid = tid >> 5;
    const int bb = blockIdx.x >> 3, ib = blockIdx.x & 7;   // ib == cluster rank
    const int nw = wid & 1, kw = wid >> 1;
    const uint32_t mbar = smb + MBAR;

    float4* wihb_s = (float4*)(smc + WIHB);
    float*  bhh_s  = (float*)(smc + BHHO);
    float*  wfc_s  = (float*)(smc + WFCO);

    // ---- mbarrier init, visible cluster-wide before any arrives ----
    if (tid == 0)
        asm volatile("mbarrier.init.shared.b64 [%0], 8;" :: "r"(mbar) : "memory");
    __syncthreads();
    asm volatile("barrier.cluster.arrive.aligned;" ::: "memory");

    // ---- weights into registers / params into SMEM (encoder phase) ----
    uint32_t Bh[6][4][2], Bl[6][4][2];
    stage_Bregs(Whh_e, Bh, Bl, ib, nw, kw, lane);
    if (tid < 96) {
        int g = tid >> 5, c = tid & 31;
        int row = g * HSZ + ib * 32 + c;
        wihb_s[tid] = make_float4(Wih_e[row * 3], Wih_e[row * 3 + 1],
                                  Wih_e[row * 3 + 2], bih_e[row]);
        bhh_s[tid] = bhh_e[row];
        wfc_s[tid] = Wfc[g * HSZ + ib * 32 + c];
    }

    // epilogue mapping: m = tid>>3 (batch local 0..31), iq = tid&7 (4 hid each)
    const int m_e = tid >> 3, iq = tid & 7;
    const int bg = bb * 32 + m_e;

    // zero h buffer 0 (production index 0)
    {
        uint2 z = make_uint2(0u, 0u);
        *(uint2*)(&g_hbf[0][0][bg * HSZ + ib * 32 + iq * 4]) = z;
        *(uint2*)(&g_hbf[1][0][bg * HSZ + ib * 32 + iq * 4]) = z;
    }
    float hprev[4] = {0.f, 0.f, 0.f, 0.f};
    __syncthreads();
    asm volatile("barrier.cluster.wait.aligned;" ::: "memory");  // inits done
    if (tid == 0) {
        #pragma unroll
        for (int r = 0; r < 8; ++r) mbar_arrive_rank(mbar, r);   // publish buf 0
    }

    // ldmatrix per-lane address bases (m-tiles at rows r0 and r0+16)
    const int lgrp = lane >> 3, lrow = lane & 7;
    const int r0 = ((lgrp & 1) << 3) + lrow;
    const int segoff = lgrp >> 1;
    const uint32_t rbh0 = smb + A_HI + r0 * 512;
    const uint32_t rbh1 = rbh0 + 16 * 512;
    const uint32_t rbl0 = smb + A_LO + r0 * 512;
    const uint32_t rbl1 = rbl0 + 16 * 512;

    for (int t = 0; t < 2 * TSZ; ++t) {
        const bool enc = t < TSZ;
        const int tt = enc ? t : t - TSZ;

        // ---- entry: every thread waits its local mbarrier (phase t) ----
        mbar_wait(mbar, (unsigned)(t & 1));

        if (t == TSZ) {   // switch to decoder weights
            stage_Bregs(Whh_d, Bh, Bl, ib, nw, kw, lane);
            if (tid < 96) {
                int g = tid >> 5, c = tid & 31;
                int row = g * HSZ + ib * 32 + c;
                wihb_s[tid] = make_float4(Wih_d[row * 3], Wih_d[row * 3 + 1],
                                          Wih_d[row * 3 + 2], bih_d[row]);
                bhh_s[tid] = bhh_d[row];
            }
        }

        // x_t prefetch (latency hides under staging)
        float x0 = 0.f, x1 = 0.f, x2 = 0.f;
        if (enc) {
            const float* xp = X_p + bg * (TSZ * 3) + tt * 3;
            x0 = xp[0]; x1 = xp[1]; x2 = xp[2];
        } else if (tt > 0) {
            const float* xp = X_f + bg * (TSZ * 3) + (tt - 1) * 3;
            x0 = xp[0]; x1 = xp[1]; x2 = xp[2];
        }

        // ---- stage A (split h) via cp.async: 2048 16B-chunks, 8/thread ----
        {
            const __nv_bfloat16* s_hi = g_hbf[0][t & 1] + bb * 32 * HSZ;
            const __nv_bfloat16* s_lo = g_hbf[1][t & 1] + bb * 32 * HSZ;
            #pragma unroll
            for (int i2 = 0; i2 < 8; ++i2) {
                int idx = tid + i2 * NTHR;
                int p = idx >> 10, rem = idx & 1023;
                int mm = rem >> 5, s = rem & 31;
                const __nv_bfloat16* src = (p ? s_lo : s_hi) + mm * HSZ + s * 8;
                uint32_t dst = smb + (p ? A_LO : A_HI)
                             + (uint32_t)(mm * 512 + ((s ^ (mm & 7)) << 4));
                cp16(dst, src);
            }
        }

        // distributed head reduce overlaps in-flight cp.asyncs
        if (t > TSZ && tid < 12) {
            int bl = ib * 4 + tid / 3, d = tid - (tid / 3) * 3;
            float s2 = bfc[d];
            #pragma unroll
            for (int p = 0; p < 8; ++p)
                s2 += g_yp[(t & 1) ^ 1][bb * 8 + p][bl][d];
            out[((bb * 32 + bl) * TSZ + (tt - 1)) * 3 + d] = s2;
        }
        asm volatile("cp.async.commit_group;");
        asm volatile("cp.async.wait_group 0;" ::: "memory");
        __syncthreads();

        // ---- tensor-core GEMM: C[m 0..31][n-half nw] partial over K-quarter ----
        float c[2][6][4];
        #pragma unroll
        for (int a = 0; a < 2; ++a)
            #pragma unroll
            for (int b2 = 0; b2 < 6; ++b2)
                #pragma unroll
                for (int d2 = 0; d2 < 4; ++d2) c[a][b2][d2] = 0.f;

        #pragma unroll
        for (int kt = 0; kt < 4; ++kt) {
            int seg = kw * 8 + kt * 2 + segoff;
            uint32_t so = (uint32_t)((seg ^ lrow) << 4);
            uint32_t ah0[4], ah1[4], al0[4], al1[4];
            ldm4(ah0, rbh0 + so);
            ldm4(ah1, rbh1 + so);
            ldm4(al0, rbl0 + so);
            ldm4(al1, rbl1 + so);
            #pragma unroll
            for (int nt = 0; nt < 6; ++nt) {
                mma16816(c[0][nt], ah0, Bh[nt][kt][0], Bh[nt][kt][1]);
                mma16816(c[1][nt], ah1, Bh[nt][kt][0], Bh[nt][kt][1]);
                mma16816(c[0][nt], al0, Bh[nt][kt][0], Bh[nt][kt][1]);
                mma16816(c[1][nt], al1, Bh[nt][kt][0], Bh[nt][kt][1]);
                mma16816(c[0][nt], ah0, Bl[nt][kt][0], Bl[nt][kt][1]);
                mma16816(c[1][nt], ah1, Bl[nt][kt][0], Bl[nt][kt][1]);
            }
        }

        // store K-partials to SMEM: cb[m*404 + kw*100 + n]
        {
            float* cb = (float*)(smc + CBUF);
            int rr = lane >> 2, cc = (lane & 3) * 2;
            #pragma unroll
            for (int mt = 0; mt < 2; ++mt)
                #pragma unroll
                for (int nt = 0; nt < 6; ++nt) {
                    int mm = mt * 16 + rr;
                    int nn = nw * 48 + nt * 8 + cc;
                    float* p0 = cb + mm * 404 + kw * 100 + nn;
                    *(float2*)p0 = make_float2(c[mt][nt][0], c[mt][nt][1]);
                    *(float2*)(p0 + 8 * 404) = make_float2(c[mt][nt][2], c[mt][nt][3]);
                }
        }
        __syncthreads();

        // ---- epilogue: reduce 4 K-partials, gates, h update ----
        const float* cb = (float*)(smc + CBUF) + m_e * 404 + iq * 4;
        float4 sR = *(const float4*)(cb);
        float4 sZ = *(const float4*)(cb + 32);
        float4 sN = *(const float4*)(cb + 64);
        #pragma unroll
        for (int k2 = 1; k2 < 4; ++k2) {
            const float* p = cb + k2 * 100;
            float4 a = *(const float4*)(p);
            float4 b2 = *(const float4*)(p + 32);
            float4 d2 = *(const float4*)(p + 64);
            sR.x += a.x;  sR.y += a.y;  sR.z += a.z;  sR.w += a.w;
            sZ.x += b2.x; sZ.y += b2.y; sZ.z += b2.z; sZ.w += b2.w;
            sN.x += d2.x; sN.y += d2.y; sN.z += d2.z; sN.w += d2.w;
        }
        float sRa[4] = {sR.x, sR.y, sR.z, sR.w};
        float sZa[4] = {sZ.x, sZ.y, sZ.z, sZ.w};
        float sNa[4] = {sN.x, sN.y, sN.z, sN.w};
        float4 bR4 = *(const float4*)(bhh_s + iq * 4);
        float4 bZ4 = *(const float4*)(bhh_s + 32 + iq * 4);
        float4 bN4 = *(const float4*)(bhh_s + 64 + iq * 4);
        float bRa[4] = {bR4.x, bR4.y, bR4.z, bR4.w};
        float bZa[4] = {bZ4.x, bZ4.y, bZ4.z, bZ4.w};
        float bNa[4] = {bN4.x, bN4.y, bN4.z, bN4.w};

        const bool addn = (t == TSZ - 1);
        float h4[4];
        #pragma unroll
        for (int q = 0; q < 4; ++q) {
            int i = iq * 4 + q;
            float4 wR = wihb_s[i], wZ = wihb_s[32 + i], wN = wihb_s[64 + i];
            float xr = wR.w + wR.x * x0 + wR.y * x1 + wR.z * x2;
            float xz = wZ.w + wZ.x * x0 + wZ.y * x1 + wZ.z * x2;
            float xn = wN.w + wN.x * x0 + wN.y * x1 + wN.z * x2;
            float r = sigf(xr + sRa[q] + bRa[q]);
            float z = sigf(xz + sZa[q] + bZa[q]);
            float n = tanhf_(xn + r * (sNa[q] + bNa[q]));
            float h = n + z * (hprev[q] - n);
            if (addn) h += noise[bg * HSZ + ib * 32 + iq * 4 + q];
            hprev[q] = h;
            h4[q] = h;
        }

        // write split h for next step (production index t+1, buf (t+1)&1)
        {
            __nv_bfloat16 h0 = __float2bfloat16(h4[0]);
            __nv_bfloat16 h1 = __float2bfloat16(h4[1]);
            __nv_bfloat16 h2 = __float2bfloat16(h4[2]);
            __nv_bfloat16 h3 = __float2bfloat16(h4[3]);
            __nv_bfloat16 l0 = __float2bfloat16(h4[0] - __bfloat162float(h0));
            __nv_bfloat16 l1 = __float2bfloat16(h4[1] - __bfloat162float(h1));
            __nv_bfloat16 l2 = __float2bfloat16(h4[2] - __bfloat162float(h2));
            __nv_bfloat16 l3 = __float2bfloat16(h4[3] - __bfloat162float(h3));
            uint32_t hiA = (uint32_t)__bfloat16_as_ushort(h0)
                         | ((uint32_t)__bfloat16_as_ushort(h1) << 16);
            uint32_t hiB = (uint32_t)__bfloat16_as_ushort(h2)
                         | ((uint32_t)__bfloat16_as_ushort(h3) << 16);
            uint32_t loA = (uint32_t)__bfloat16_as_ushort(l0)
                         | ((uint32_t)__bfloat16_as_ushort(l1) << 16);
            uint32_t loB = (uint32_t)__bfloat16_as_ushort(l2)
                         | ((uint32_t)__bfloat16_as_ushort(l3) << 16);
            int off = bg * HSZ + ib * 32 + iq * 4;
            *(uint2*)(&g_hbf[0][(t + 1) & 1][off]) = make_uint2(hiA, hiB);
            *(uint2*)(&g_hbf[1][(t + 1) & 1][off]) = make_uint2(loA, loB);
        }

        // fused FC head partial (decoder): reduce over 8 iq lanes
        if (!enc) {
            float4 w0 = *(const float4*)(wfc_s + iq * 4);
            float4 w1 = *(const float4*)(wfc_s + 32 + iq * 4);
            float4 w2 = *(const float4*)(wfc_s + 64 + iq * 4);
            float y0 = h4[0] * w0.x + h4[1] * w0.y + h4[2] * w0.z + h4[3] * w0.w;
            float y1 = h4[0] * w1.x + h4[1] * w1.y + h4[2] * w1.z + h4[3] * w1.w;
            float y2 = h4[0] * w2.x + h4[1] * w2.y + h4[2] * w2.z + h4[3] * w2.w;
            #pragma unroll
            for (int o = 4; o > 0; o >>= 1) {
                y0 += __shfl_xor_sync(0xffffffffu, y0, o);
                y1 += __shfl_xor_sync(0xffffffffu, y1, o);
                y2 += __shfl_xor_sync(0xffffffffu, y2, o);
            }
            if (iq == 0)
                *(float4*)(&g_yp[t & 1][blockIdx.x][m_e][0]) =
                    make_float4(y0, y1, y2, 0.f);
        }

        // publish production index t+1: cluster-wide release arrives
        __syncthreads();
        if (tid == 0) {
            #pragma unroll
            for (int r = 0; r < 8; ++r) mbar_arrive_rank(mbar, r);
        }
    }

    // final head reduction for tstep = 255 (partials at t=511, buf par=1):
    // wait phase #512 (completion of the t=511 arrive set), parity 512&1 = 0
    mbar_wait(mbar, 0u);
    if (tid < 12) {
        int bl = ib * 4 + tid / 3, d = tid - (tid / 3) * 3;
        float s2 = bfc[d];
        #pragma unroll
        for (int p = 0; p < 8; ++p)
            s2 += g_yp[1][bb * 8 + p][bl][d];
        out[((bb * 32 + bl) * TSZ + (TSZ - 1)) * 3 + d] = s2;
    }
    // mbarriers die with the launch; re-initialized next replay (no reset).
}

extern "C" void kernel_launch(void* const* d_in, const int* in_sizes, int n_in,
                              void* d_out, int out_size) {
    const float* X_p   = (const float*)d_in[0];
    const float* X_f   = (const float*)d_in[1];
    const float* noise = (const float*)d_in[2];
    const float* Wih_e = (const float*)d_in[3];
    const float* Whh_e = (const float*)d_in[4];
    const float* bih_e = (const float*)d_in[5];
    const float* bhh_e = (const float*)d_in[6];
    const float* Wih_d = (const float*)d_in[7];
    const float* Whh_d = (const float*)d_in[8];
    const float* bih_d = (const float*)d_in[9];
    const float* bhh_d = (const float*)d_in[10];
    const float* Wfc   = (const float*)d_in[11];
    const float* bfc   = (const float*)d_in[12];
    float* out = (float*)d_out;

    cudaFuncSetAttribute(netg_mma, cudaFuncAttributeMaxDynamicSharedMemorySize,
                         SMEM_BYTES);
    netg_mma<<<NCTA, NTHR, SMEM_BYTES>>>(
        X_p, X_f, noise, Wih_e, Whh_e, bih_e, bhh_e,
        Wih_d, Whh_d, bih_d, bhh_d, Wfc, bfc, out);
}

// round 14
// speedup vs baseline: 2.2031x; 2.2031x over previous
#include <cuda_runtime.h>
#include <cuda_bf16.h>
#include <cstdint>

// NetG: encoder GRU -> +noise -> decoder GRU -> FC head.
// mma.sync.m16n8k16 bf16 x3-split GEMM, R10 sync skeleton (REDG counter,
// single poller, 4 CTA syncs). R14: 128-thread CTAs (M=16), occupancy 2 —
// two independent batch-group chains per SM overlap their barrier waits.
// 256 CTAs = 32 groups x 8 hidden-blocks.

#define TSZ 256
#define HSZ 256
#define BSZ 512
#define NCTA 256
#define NTHR 128

// smem byte offsets
#define A_HI 0                // 16 x 512B swizzled bf16 (Ah)
#define A_LO 8192             // Al
#define CBUF 16384            // float [m stride 204][kw stride 100][n 96]
#define WIHB 29440            // 96 x float4 {w0,w1,w2,bih}
#define BHHO 30976            // 96 floats bhh
#define WFCO 31360            // 96 floats wfc (3 x 32)
#define SMEM_BYTES 31744

__device__ __nv_bfloat16 g_hbf[2][2][BSZ * HSZ];  // [hi/lo][buf][b*256+j]
__device__ float g_yp[2][NCTA][16][4];            // head partials
__device__ unsigned g_cnt[32][32];                // [bb][pad] monotonic counter

__device__ __forceinline__ uint32_t smem_u32(const void* p) {
    uint32_t a;
    asm("{ .reg .u64 t; cvta.to.shared.u64 t, %1; cvt.u32.u64 %0, t; }"
        : "=r"(a) : "l"(p));
    return a;
}
__device__ __forceinline__ void ldm4(uint32_t* r, uint32_t addr) {
    asm volatile("ldmatrix.sync.aligned.m8n8.x4.shared.b16 {%0,%1,%2,%3}, [%4];"
        : "=r"(r[0]), "=r"(r[1]), "=r"(r[2]), "=r"(r[3]) : "r"(addr));
}
__device__ __forceinline__ void mma16816(float* c, const uint32_t* a,
                                         uint32_t b0, uint32_t b1) {
    asm volatile(
        "mma.sync.aligned.m16n8k16.row.col.f32.bf16.bf16.f32 "
        "{%0,%1,%2,%3}, {%4,%5,%6,%7}, {%8,%9}, {%0,%1,%2,%3};"
        : "+f"(c[0]), "+f"(c[1]), "+f"(c[2]), "+f"(c[3])
        : "r"(a[0]), "r"(a[1]), "r"(a[2]), "r"(a[3]), "r"(b0), "r"(b1));
}
__device__ __forceinline__ void arrive(unsigned* cnt) {
    asm volatile("red.add.release.gpu.u32 [%0], 1;" :: "l"(cnt) : "memory");
}
__device__ __forceinline__ void wait_ge(const unsigned* cnt, unsigned target) {
    unsigned v;
    do {
        asm volatile("ld.acquire.gpu.u32 %0, [%1];" : "=r"(v) : "l"(cnt) : "memory");
    } while ((int)(v - target) < 0);
}
__device__ __forceinline__ float sigf(float x) {
    return __fdividef(1.0f, 1.0f + __expf(-x));
}
__device__ __forceinline__ float tanhf_(float x) {
    return 1.0f - __fdividef(2.0f, __expf(2.0f * x) + 1.0f);
}

// Build this warp's B fragments (weights) in registers, split hi/lo bf16.
// Warp covers n-rows [nw*48, nw*48+48), k-half [kw*128, kw*128+128).
__device__ __forceinline__ void stage_Bregs(
    const float* __restrict__ W, uint32_t Bh[6][8][2], uint32_t Bl[6][8][2],
    int ib, int nw, int kw, int lane)
{
    const int nr = lane >> 2, kc = (lane & 3) * 2;
    #pragma unroll
    for (int nt = 0; nt < 6; ++nt) {
        int n = nw * 48 + nt * 8 + nr;
        int g = n >> 5, c = n & 31;
        const float* row = W + (g * HSZ + ib * 32 + c) * HSZ;
        #pragma unroll
        for (int kt = 0; kt < 8; ++kt) {
            #pragma unroll
            for (int rg = 0; rg < 2; ++rg) {
                int kk = kw * 128 + kt * 16 + rg * 8 + kc;
                float2 w = *(const float2*)(row + kk);
                __nv_bfloat16 h0 = __float2bfloat16(w.x);
                __nv_bfloat16 h1 = __float2bfloat16(w.y);
                __nv_bfloat16 l0 = __float2bfloat16(w.x - __bfloat162float(h0));
                __nv_bfloat16 l1 = __float2bfloat16(w.y - __bfloat162float(h1));
                Bh[nt][kt][rg] = (uint32_t)__bfloat16_as_ushort(h0)
                               | ((uint32_t)__bfloat16_as_ushort(h1) << 16);
                Bl[nt][kt][rg] = (uint32_t)__bfloat16_as_ushort(l0)
                               | ((uint32_t)__bfloat16_as_ushort(l1) << 16);
            }
        }
    }
}

extern "C" __global__ void __launch_bounds__(NTHR, 2)
netg_mma(const float* __restrict__ X_p, const float* __restrict__ X_f,
         const float* __restrict__ noise,
         const float* __restrict__ Wih_e, const float* __restrict__ Whh_e,
         const float* __restrict__ bih_e, const float* __restrict__ bhh_e,
         const float* __restrict__ Wih_d, const float* __restrict__ Whh_d,
         const float* __restrict__ bih_d, const float* __restrict__ bhh_d,
         const float* __restrict__ Wfc,   const float* __restrict__ bfc,
         float* __restrict__ out)
{
    extern __shared__ char smc[];
    const uint32_t smb = smem_u32(smc);
    const int tid = threadIdx.x, lane = tid & 31, wid = tid >> 5;
    const int bb = blockIdx.x >> 3, ib = blockIdx.x & 7;   // 32 groups x 8 blocks
    const int nw = wid & 1, kw = wid >> 1;                 // 2 n-halves x 2 k-halves

    float4* wihb_s = (float4*)(smc + WIHB);
    float*  bhh_s  = (float*)(smc + BHHO);
    float*  wfc_s  = (float*)(smc + WFCO);
    unsigned* cnt  = &g_cnt[bb][0];

    // ---- weights into registers / params into SMEM (encoder phase) ----
    uint32_t Bh[6][8][2], Bl[6][8][2];
    stage_Bregs(Whh_e, Bh, Bl, ib, nw, kw, lane);
    if (tid < 96) {
        int g = tid >> 5, c = tid & 31;
        int row = g * HSZ + ib * 32 + c;
        wihb_s[tid] = make_float4(Wih_e[row * 3], Wih_e[row * 3 + 1],
                                  Wih_e[row * 3 + 2], bih_e[row]);
        bhh_s[tid] = bhh_e[row];
        wfc_s[tid] = Wfc[g * HSZ + ib * 32 + c];
    }

    // epilogue mapping: m = tid>>3 (batch local 0..15), iq = tid&7 (4 hid each)
    const int m_e = tid >> 3, iq = tid & 7;
    const int bg = bb * 16 + m_e;

    // zero h buffer 0 (production index 0)
    {
        uint2 z = make_uint2(0u, 0u);
        *(uint2*)(&g_hbf[0][0][bg * HSZ + ib * 32 + iq * 4]) = z;
        *(uint2*)(&g_hbf[1][0][bg * HSZ + ib * 32 + iq * 4]) = z;
    }
    float hprev[4] = {0.f, 0.f, 0.f, 0.f};
    __syncthreads();
    if (tid == 0) arrive(cnt);   // init arrival: buffer 0 published

    // ldmatrix per-lane address bases (single m16 tile, rows 0..15)
    const int lgrp = lane >> 3, lrow = lane & 7;
    const int r0 = ((lgrp & 1) << 3) + lrow;
    const int segoff = lgrp >> 1;
    const uint32_t rbh0 = smb + A_HI + r0 * 512;
    const uint32_t rbl0 = smb + A_LO + r0 * 512;

    for (int t = 0; t < 2 * TSZ; ++t) {
        const bool enc = t < TSZ;
        const int tt = enc ? t : t - TSZ;

        // ---- entry barrier: all 8 producers of this group reached index t ----
        if (tid == 0) wait_ge(cnt, 8u * (unsigned)(t + 1));
        __syncthreads();

        if (t == TSZ) {   // switch to decoder weights
            stage_Bregs(Whh_d, Bh, Bl, ib, nw, kw, lane);
            if (tid < 96) {
                int g = tid >> 5, c = tid & 31;
                int row = g * HSZ + ib * 32 + c;
                wihb_s[tid] = make_float4(Wih_d[row * 3], Wih_d[row * 3 + 1],
                                          Wih_d[row * 3 + 2], bih_d[row]);
                bhh_s[tid] = bhh_d[row];
            }
        }

        // x_t prefetch (latency hides under staging)
        float x0 = 0.f, x1 = 0.f, x2 = 0.f;
        if (enc) {
            const float* xp = X_p + bg * (TSZ * 3) + tt * 3;
            x0 = xp[0]; x1 = xp[1]; x2 = xp[2];
        } else if (tt > 0) {
            const float* xp = X_f + bg * (TSZ * 3) + (tt - 1) * 3;
            x0 = xp[0]; x1 = xp[1]; x2 = xp[2];
        }

        // distributed head reduce: this CTA's 2 batches of decoder step tt-1
        if (t > TSZ && tid < 6) {
            int bl = ib * 2 + tid / 3, d = tid - (tid / 3) * 3;
            float s2 = bfc[d];
            #pragma unroll
            for (int p = 0; p < 8; ++p)
                s2 += g_yp[(t & 1) ^ 1][bb * 8 + p][bl][d];
            out[((bb * 16 + bl) * TSZ + (tt - 1)) * 3 + d] = s2;
        }

        // ---- stage A (split h): 1024 16B-chunks, 8 per thread ----
        {
            const __nv_bfloat16* s_hi = g_hbf[0][t & 1] + bb * 16 * HSZ;
            const __nv_bfloat16* s_lo = g_hbf[1][t & 1] + bb * 16 * HSZ;
            #pragma unroll
            for (int i2 = 0; i2 < 8; ++i2) {
                int idx = tid + i2 * NTHR;
                int p = idx >> 9, rem = idx & 511;
                int mm = rem >> 5, s = rem & 31;
                const __nv_bfloat16* src = (p ? s_lo : s_hi) + mm * HSZ + s * 8;
                uint4 v = *(const uint4*)src;
                char* db = smc + (p ? A_LO : A_HI);
                *(uint4*)(db + mm * 512 + ((s ^ (mm & 7)) << 4)) = v;
            }
        }
        __syncthreads();

        // ---- tensor-core GEMM: C[m 0..15][n-half nw] partial over K-half ----
        float c[6][4];
        #pragma unroll
        for (int b2 = 0; b2 < 6; ++b2)
            #pragma unroll
            for (int d2 = 0; d2 < 4; ++d2) c[b2][d2] = 0.f;

        #pragma unroll
        for (int kt = 0; kt < 8; ++kt) {
            int seg = kw * 16 + kt * 2 + segoff;
            uint32_t so = (uint32_t)((seg ^ lrow) << 4);
            uint32_t ah[4], al[4];
            ldm4(ah, rbh0 + so);
            ldm4(al, rbl0 + so);
            #pragma unroll
            for (int nt = 0; nt < 6; ++nt) {
                mma16816(c[nt], ah, Bh[nt][kt][0], Bh[nt][kt][1]);
                mma16816(c[nt], al, Bh[nt][kt][0], Bh[nt][kt][1]);
                mma16816(c[nt], ah, Bl[nt][kt][0], Bl[nt][kt][1]);
            }
        }

        // store K-partials to SMEM: cb[m*204 + kw*100 + n]
        {
            float* cb = (float*)(smc + CBUF);
            int rr = lane >> 2, cc = (lane & 3) * 2;
            #pragma unroll
            for (int nt = 0; nt < 6; ++nt) {
                int nn = nw * 48 + nt * 8 + cc;
                float* p0 = cb + rr * 204 + kw * 100 + nn;
                *(float2*)p0 = make_float2(c[nt][0], c[nt][1]);
                *(float2*)(p0 + 8 * 204) = make_float2(c[nt][2], c[nt][3]);
            }
        }
        __syncthreads();

        // ---- epilogue: reduce 2 K-partials, gates, h update ----
        const float* cb = (float*)(smc + CBUF) + m_e * 204 + iq * 4;
        float4 sR = *(const float4*)(cb);
        float4 sZ = *(const float4*)(cb + 32);
        float4 sN = *(const float4*)(cb + 64);
        {
            const float* p = cb + 100;
            float4 a = *(const float4*)(p);
            float4 b2 = *(const float4*)(p + 32);
            float4 d2 = *(const float4*)(p + 64);
            sR.x += a.x;  sR.y += a.y;  sR.z += a.z;  sR.w += a.w;
            sZ.x += b2.x; sZ.y += b2.y; sZ.z += b2.z; sZ.w += b2.w;
            sN.x += d2.x; sN.y += d2.y; sN.z += d2.z; sN.w += d2.w;
        }
        float sRa[4] = {sR.x, sR.y, sR.z, sR.w};
        float sZa[4] = {sZ.x, sZ.y, sZ.z, sZ.w};
        float sNa[4] = {sN.x, sN.y, sN.z, sN.w};
        float4 bR4 = *(const float4*)(bhh_s + iq * 4);
        float4 bZ4 = *(const float4*)(bhh_s + 32 + iq * 4);
        float4 bN4 = *(const float4*)(bhh_s + 64 + iq * 4);
        float bRa[4] = {bR4.x, bR4.y, bR4.z, bR4.w};
        float bZa[4] = {bZ4.x, bZ4.y, bZ4.z, bZ4.w};
        float bNa[4] = {bN4.x, bN4.y, bN4.z, bN4.w};

        const bool addn = (t == TSZ - 1);
        float h4[4];
        #pragma unroll
        for (int q = 0; q < 4; ++q) {
            int i = iq * 4 + q;
            float4 wR = wihb_s[i], wZ = wihb_s[32 + i], wN = wihb_s[64 + i];
            float xr = wR.w + wR.x * x0 + wR.y * x1 + wR.z * x2;
            float xz = wZ.w + wZ.x * x0 + wZ.y * x1 + wZ.z * x2;
            float xn = wN.w + wN.x * x0 + wN.y * x1 + wN.z * x2;
            float r = sigf(xr + sRa[q] + bRa[q]);
            float z = sigf(xz + sZa[q] + bZa[q]);
            float n = tanhf_(xn + r * (sNa[q] + bNa[q]));
            float h = n + z * (hprev[q] - n);
            if (addn) h += noise[bg * HSZ + ib * 32 + iq * 4 + q];
            hprev[q] = h;
            h4[q] = h;
        }

        // write split h for next step (production index t+1, buf (t+1)&1)
        {
            __nv_bfloat16 h0 = __float2bfloat16(h4[0]);
            __nv_bfloat16 h1 = __float2bfloat16(h4[1]);
            __nv_bfloat16 h2 = __float2bfloat16(h4[2]);
            __nv_bfloat16 h3 = __float2bfloat16(h4[3]);
            __nv_bfloat16 l0 = __float2bfloat16(h4[0] - __bfloat162float(h0));
            __nv_bfloat16 l1 = __float2bfloat16(h4[1] - __bfloat162float(h1));
            __nv_bfloat16 l2 = __float2bfloat16(h4[2] - __bfloat162float(h2));
            __nv_bfloat16 l3 = __float2bfloat16(h4[3] - __bfloat162float(h3));
            uint32_t hiA = (uint32_t)__bfloat16_as_ushort(h0)
                         | ((uint32_t)__bfloat16_as_ushort(h1) << 16);
            uint32_t hiB = (uint32_t)__bfloat16_as_ushort(h2)
                         | ((uint32_t)__bfloat16_as_ushort(h3) << 16);
            uint32_t loA = (uint32_t)__bfloat16_as_ushort(l0)
                         | ((uint32_t)__bfloat16_as_ushort(l1) << 16);
            uint32_t loB = (uint32_t)__bfloat16_as_ushort(l2)
                         | ((uint32_t)__bfloat16_as_ushort(l3) << 16);
            int off = bg * HSZ + ib * 32 + iq * 4;
            *(uint2*)(&g_hbf[0][(t + 1) & 1][off]) = make_uint2(hiA, hiB);
            *(uint2*)(&g_hbf[1][(t + 1) & 1][off]) = make_uint2(loA, loB);
        }

        // fused FC head partial (decoder): reduce over 8 iq lanes
        if (!enc) {
            float4 w0 = *(const float4*)(wfc_s + iq * 4);
            float4 w1 = *(const float4*)(wfc_s + 32 + iq * 4);
            float4 w2 = *(const float4*)(wfc_s + 64 + iq * 4);
            float y0 = h4[0] * w0.x + h4[1] * w0.y + h4[2] * w0.z + h4[3] * w0.w;
            float y1 = h4[0] * w1.x + h4[1] * w1.y + h4[2] * w1.z + h4[3] * w1.w;
            float y2 = h4[0] * w2.x + h4[1] * w2.y + h4[2] * w2.z + h4[3] * w2.w;
            #pragma unroll
            for (int o = 4; o > 0; o >>= 1) {
                y0 += __shfl_xor_sync(0xffffffffu, y0, o);
                y1 += __shfl_xor_sync(0xffffffffu, y1, o);
                y2 += __shfl_xor_sync(0xffffffffu, y2, o);
            }
            if (iq == 0)
                *(float4*)(&g_yp[t & 1][blockIdx.x][m_e][0]) =
                    make_float4(y0, y1, y2, 0.f);
        }

        // publish production index t+1
        __syncthreads();
        if (tid == 0) arrive(cnt);
    }

    // final head reduction for tstep = 255 (partials at t=511, buf par=1)
    if (tid == 0) wait_ge(cnt, 8u * 513u);
    __syncthreads();
    if (tid < 6) {
        int bl = ib * 2 + tid / 3, d = tid - (tid / 3) * 3;
        float s2 = bfc[d];
        #pragma unroll
        for (int p = 0; p < 8; ++p)
            s2 += g_yp[1][bb * 8 + p][bl][d];
        out[((bb * 16 + bl) * TSZ + (TSZ - 1)) * 3 + d] = s2;
    }
    __syncthreads();
    if (tid == 0) arrive(cnt);

    // counter reset for graph replay: ib==0 waits for all final arrivals,
    // then stores 0 (no CTA reads the counter after its last arrive).
    if (ib == 0 && tid == 0) {
        wait_ge(cnt, 8u * 514u);
        asm volatile("st.release.gpu.u32 [%0], %1;" :: "l"(cnt), "r"(0u) : "memory");
    }
}

extern "C" void kernel_launch(void* const* d_in, const int* in_sizes, int n_in,
                              void* d_out, int out_size) {
    const float* X_p   = (const float*)d_in[0];
    const float* X_f   = (const float*)d_in[1];
    const float* noise = (const float*)d_in[2];
    const float* Wih_e = (const float*)d_in[3];
    const float* Whh_e = (const float*)d_in[4];
    const float* bih_e = (const float*)d_in[5];
    const float* bhh_e = (const float*)d_in[6];
    const float* Wih_d = (const float*)d_in[7];
    const float* Whh_d = (const float*)d_in[8];
    const float* bih_d = (const float*)d_in[9];
    const float* bhh_d = (const float*)d_in[10];
    const float* Wfc   = (const float*)d_in[11];
    const float* bfc   = (const float*)d_in[12];
    float* out = (float*)d_out;

    cudaFuncSetAttribute(netg_mma, cudaFuncAttributeMaxDynamicSharedMemorySize,
                         SMEM_BYTES);
    netg_mma<<<NCTA, NTHR, SMEM_BYTES>>>(
        X_p, X_f, noise, Wih_e, Whh_e, bih_e, bhh_e,
        Wih_d, Whh_d, bih_d, bhh_d, Wfc, bfc, out);
}

// round 15
// speedup vs baseline: 2.4282x; 1.1022x over previous
#include <cuda_runtime.h>
#include <cuda_bf16.h>
#include <cstdint>

// NetG: encoder GRU -> +noise -> decoder GRU -> FC head.
// mma.sync.m16n8k16 bf16 x3-split GEMM, R10 counter sync, R14 geometry
// (M=16, 128 thr, occ 2, 32 groups x 8 CTAs). R15: full-K per warp with a
// gate-interleaved B mapping -> C complete in registers, epilogue fully
// register-local, CBUF deleted (one fewer CTA sync, no cross-warp remap).

#define TSZ 256
#define HSZ 256
#define BSZ 512
#define NCTA 256
#define NTHR 128

// smem byte offsets
#define A_HI 0                // 16 x 512B swizzled bf16 (Ah)
#define A_LO 8192             // Al
#define WIHB 16384            // 96 x float4 {w0,w1,w2,bih}  (g*32+c)
#define BHHO 17920            // 96 floats bhh
#define WFCO 18304            // 96 floats wfc (d*32+c)
#define XS   18688            // 16*3 floats x_t
#define SMEM_BYTES 18880

__device__ __nv_bfloat16 g_hbf[2][2][BSZ * HSZ];  // [hi/lo][buf][b*256+j]
__device__ float4 g_yp[2][NCTA][4][16];           // head partials per warp
__device__ unsigned g_cnt[32][32];                // [bb][pad] monotonic counter

__device__ __forceinline__ uint32_t smem_u32(const void* p) {
    uint32_t a;
    asm("{ .reg .u64 t; cvta.to.shared.u64 t, %1; cvt.u32.u64 %0, t; }"
        : "=r"(a) : "l"(p));
    return a;
}
__device__ __forceinline__ void ldm4(uint32_t* r, uint32_t addr) {
    asm volatile("ldmatrix.sync.aligned.m8n8.x4.shared.b16 {%0,%1,%2,%3}, [%4];"
        : "=r"(r[0]), "=r"(r[1]), "=r"(r[2]), "=r"(r[3]) : "r"(addr));
}
__device__ __forceinline__ void mma16816(float* c, const uint32_t* a,
                                         uint32_t b0, uint32_t b1) {
    asm volatile(
        "mma.sync.aligned.m16n8k16.row.col.f32.bf16.bf16.f32 "
        "{%0,%1,%2,%3}, {%4,%5,%6,%7}, {%8,%9}, {%0,%1,%2,%3};"
        : "+f"(c[0]), "+f"(c[1]), "+f"(c[2]), "+f"(c[3])
        : "r"(a[0]), "r"(a[1]), "r"(a[2]), "r"(a[3]), "r"(b0), "r"(b1));
}
__device__ __forceinline__ void arrive(unsigned* cnt) {
    asm volatile("red.add.release.gpu.u32 [%0], 1;" :: "l"(cnt) : "memory");
}
__device__ __forceinline__ void wait_ge(const unsigned* cnt, unsigned target) {
    unsigned v;
    do {
        asm volatile("ld.acquire.gpu.u32 %0, [%1];" : "=r"(v) : "l"(cnt) : "memory");
    } while ((int)(v - target) < 0);
}
__device__ __forceinline__ float sigf(float x) {
    return __fdividef(1.0f, 1.0f + __expf(-x));
}
__device__ __forceinline__ float tanhf_(float x) {
    return 1.0f - __fdividef(2.0f, __expf(2.0f * x) + 1.0f);
}

// Gate-interleaved B fragments: warp w covers 24 N-rows (3 tiles), full K.
// Fragment (nt, nr=lane>>2) maps to (col, gate) so C-fragment threads own
// complete r/z/n triples for cols 2q, 2q+1 (q = lane&3).
__device__ __forceinline__ void stage_Bregs(
    const float* __restrict__ W, uint32_t Bh[3][16][2], uint32_t Bl[3][16][2],
    int ib, int w, int lane)
{
    const int nr = lane >> 2, kc = (lane & 3) * 2;
    const int odd = nr & 1, q2 = nr >> 1;
    #pragma unroll
    for (int nt = 0; nt < 3; ++nt) {
        int idx = nt * 2 + odd;
        int hi3 = (idx >= 3);
        int cl = q2 * 2 + hi3;
        int g = idx - 3 * hi3;
        const float* row = W + (g * HSZ + ib * 32 + w * 8 + cl) * HSZ;
        #pragma unroll
        for (int kt = 0; kt < 16; ++kt) {
            #pragma unroll
            for (int rg = 0; rg < 2; ++rg) {
                int kk = kt * 16 + rg * 8 + kc;
                float2 wv = *(const float2*)(row + kk);
                __nv_bfloat16 h0 = __float2bfloat16(wv.x);
                __nv_bfloat16 h1 = __float2bfloat16(wv.y);
                __nv_bfloat16 l0 = __float2bfloat16(wv.x - __bfloat162float(h0));
                __nv_bfloat16 l1 = __float2bfloat16(wv.y - __bfloat162float(h1));
                Bh[nt][kt][rg] = (uint32_t)__bfloat16_as_ushort(h0)
                               | ((uint32_t)__bfloat16_as_ushort(h1) << 16);
                Bl[nt][kt][rg] = (uint32_t)__bfloat16_as_ushort(l0)
                               | ((uint32_t)__bfloat16_as_ushort(l1) << 16);
            }
        }
    }
}

extern "C" __global__ void __launch_bounds__(NTHR, 2)
netg_mma(const float* __restrict__ X_p, const float* __restrict__ X_f,
         const float* __restrict__ noise,
         const float* __restrict__ Wih_e, const float* __restrict__ Whh_e,
         const float* __restrict__ bih_e, const float* __restrict__ bhh_e,
         const float* __restrict__ Wih_d, const float* __restrict__ Whh_d,
         const float* __restrict__ bih_d, const float* __restrict__ bhh_d,
         const float* __restrict__ Wfc,   const float* __restrict__ bfc,
         float* __restrict__ out)
{
    extern __shared__ char smc[];
    const uint32_t smb = smem_u32(smc);
    const int tid = threadIdx.x, lane = tid & 31, w = tid >> 5;
    const int bb = blockIdx.x >> 3, ib = blockIdx.x & 7;
    const int rr = lane >> 2, q = lane & 3;

    float4* wihb_s = (float4*)(smc + WIHB);
    float*  bhh_s  = (float*)(smc + BHHO);
    float*  wfc_s  = (float*)(smc + WFCO);
    float*  x_s    = (float*)(smc + XS);
    unsigned* cnt  = &g_cnt[bb][0];

    // ---- weights into registers / params into SMEM (encoder phase) ----
    uint32_t Bh[3][16][2], Bl[3][16][2];
    stage_Bregs(Whh_e, Bh, Bl, ib, w, lane);
    if (tid < 96) {
        int g = tid >> 5, c = tid & 31;
        int row = g * HSZ + ib * 32 + c;
        wihb_s[tid] = make_float4(Wih_e[row * 3], Wih_e[row * 3 + 1],
                                  Wih_e[row * 3 + 2], bih_e[row]);
        bhh_s[tid] = bhh_e[row];
        wfc_s[tid] = Wfc[g * HSZ + ib * 32 + c];
    }

    // this thread's epilogue ownership: batches rr, rr+8; cols lc0, lc0+1
    const int lc0 = w * 8 + q * 2;
    const int bg0 = bb * 16 + rr, bg1 = bg0 + 8;

    // zero h buffer 0 (production index 0): cols lc0..lc0+1 of both batches
    {
        uint32_t z = 0;
        #pragma unroll
        for (int p = 0; p < 2; ++p) {
            *(uint32_t*)(&g_hbf[p][0][bg0 * HSZ + ib * 32 + lc0]) = z;
            *(uint32_t*)(&g_hbf[p][0][bg1 * HSZ + ib * 32 + lc0]) = z;
        }
    }
    float hp[2][2] = {{0.f, 0.f}, {0.f, 0.f}};   // [m(0:rr,1:rr+8)][col]
    __syncthreads();
    if (tid == 0) arrive(cnt);   // init arrival: buffer 0 published

    // ldmatrix per-lane address bases (m16 x k16 via x4)
    const int lgrp = lane >> 3, lrow = lane & 7;
    const int r0 = ((lgrp & 1) << 3) + lrow;
    const int segoff = lgrp >> 1;
    const uint32_t rbh0 = smb + A_HI + r0 * 512;
    const uint32_t rbl0 = smb + A_LO + r0 * 512;

    for (int t = 0; t < 2 * TSZ; ++t) {
        const bool enc = t < TSZ;
        const int tt = enc ? t : t - TSZ;

        // ---- entry barrier: all 8 producers of this group reached index t ----
        if (tid == 0) wait_ge(cnt, 8u * (unsigned)(t + 1));
        __syncthreads();

        if (t == TSZ) {   // switch to decoder weights
            stage_Bregs(Whh_d, Bh, Bl, ib, w, lane);
            if (tid < 96) {
                int g = tid >> 5, c = tid & 31;
                int row = g * HSZ + ib * 32 + c;
                wihb_s[tid] = make_float4(Wih_d[row * 3], Wih_d[row * 3 + 1],
                                          Wih_d[row * 3 + 2], bih_d[row]);
                bhh_s[tid] = bhh_d[row];
            }
        }

        // stage x_t into SMEM (decoder input = right-shifted X_f)
        if (tid < 48) {
            int bl = tid / 3, d = tid - bl * 3;
            float v = 0.f;
            if (enc)          v = X_p[(bb * 16 + bl) * (TSZ * 3) + tt * 3 + d];
            else if (tt > 0)  v = X_f[(bb * 16 + bl) * (TSZ * 3) + (tt - 1) * 3 + d];
            x_s[bl * 3 + d] = v;
        }

        // distributed head reduce: this CTA's 2 batches of decoder step tt-1
        if (t > TSZ && tid < 2) {
            int bl = ib * 2 + tid;
            float s0 = bfc[0], s1 = bfc[1], s2 = bfc[2];
            #pragma unroll
            for (int p = 0; p < 8; ++p)
                #pragma unroll
                for (int ww = 0; ww < 4; ++ww) {
                    float4 v = g_yp[(t & 1) ^ 1][bb * 8 + p][ww][bl];
                    s0 += v.x; s1 += v.y; s2 += v.z;
                }
            float* po = &out[((bb * 16 + bl) * TSZ + (tt - 1)) * 3];
            po[0] = s0; po[1] = s1; po[2] = s2;
        }

        // ---- stage A (split h): 1024 16B-chunks, 8 per thread ----
        {
            const __nv_bfloat16* s_hi = g_hbf[0][t & 1] + bb * 16 * HSZ;
            const __nv_bfloat16* s_lo = g_hbf[1][t & 1] + bb * 16 * HSZ;
            #pragma unroll
            for (int i2 = 0; i2 < 8; ++i2) {
                int idx = tid + i2 * NTHR;
                int p = idx >> 9, rem = idx & 511;
                int mm = rem >> 5, s = rem & 31;
                const __nv_bfloat16* src = (p ? s_lo : s_hi) + mm * HSZ + s * 8;
                uint4 v = *(const uint4*)src;
                char* db = smc + (p ? A_LO : A_HI);
                *(uint4*)(db + mm * 512 + ((s ^ (mm & 7)) << 4)) = v;
            }
        }
        __syncthreads();

        // ---- tensor-core GEMM: full K per warp, C complete in registers ----
        float c[3][4];
        #pragma unroll
        for (int nt = 0; nt < 3; ++nt)
            #pragma unroll
            for (int d2 = 0; d2 < 4; ++d2) c[nt][d2] = 0.f;

        #pragma unroll
        for (int kt = 0; kt < 16; ++kt) {
            int seg = kt * 2 + segoff;
            uint32_t so = (uint32_t)((seg ^ lrow) << 4);
            uint32_t ah[4], al[4];
            ldm4(ah, rbh0 + so);
            ldm4(al, rbl0 + so);
            #pragma unroll
            for (int nt = 0; nt < 3; ++nt) {
                mma16816(c[nt], ah, Bh[nt][kt][0], Bh[nt][kt][1]);
                mma16816(c[nt], al, Bh[nt][kt][0], Bh[nt][kt][1]);
                mma16816(c[nt], ah, Bl[nt][kt][0], Bl[nt][kt][1]);
            }
        }

        // ---- register-local epilogue: gates, h update, h store, head ----
        // fragment -> gates: m-row 0 (rr) uses c[*][0..1], m-row 1 (rr+8) c[*][2..3]
        //  col lc0:   r=c[0][f0], z=c[0][f1], n=c[1][f0]
        //  col lc0+1: r=c[1][f1], z=c[2][f0], n=c[2][f1]
        const bool addn = (t == TSZ - 1);
        float4 wA[2], wB[2];   // [col], param rows for this thread's 2 cols
        float bhr[2], bhz[2], bhn[2];
        #pragma unroll
        for (int cc = 0; cc < 2; ++cc) {
            int lc = lc0 + cc;
            wA[cc] = wihb_s[lc];          // r gate params
            wB[cc] = wihb_s[32 + lc];     // z
            bhr[cc] = bhh_s[lc];
            bhz[cc] = bhh_s[32 + lc];
            bhn[cc] = bhh_s[64 + lc];
        }
        float4 wN0 = wihb_s[64 + lc0], wN1 = wihb_s[64 + lc0 + 1];

        float hnew[2][2];
        #pragma unroll
        for (int mi = 0; mi < 2; ++mi) {
            int bl = rr + mi * 8;
            int f0 = mi * 2, f1 = mi * 2 + 1;
            float x0 = x_s[bl * 3], x1 = x_s[bl * 3 + 1], x2 = x_s[bl * 3 + 2];
            float pr0 = c[0][f0], pz0 = c[0][f1], pn0 = c[1][f0];
            float pr1 = c[1][f1], pz1 = c[2][f0], pn1 = c[2][f1];
            // col 0
            {
                float xr = wA[0].w + wA[0].x * x0 + wA[0].y * x1 + wA[0].z * x2;
                float xz = wB[0].w + wB[0].x * x0 + wB[0].y * x1 + wB[0].z * x2;
                float xn = wN0.w + wN0.x * x0 + wN0.y * x1 + wN0.z * x2;
                float r = sigf(xr + pr0 + bhr[0]);
                float z = sigf(xz + pz0 + bhz[0]);
                float n = tanhf_(xn + r * (pn0 + bhn[0]));
                float h = n + z * (hp[mi][0] - n);
                if (addn) h += noise[(bb * 16 + bl) * HSZ + ib * 32 + lc0];
                hp[mi][0] = h; hnew[mi][0] = h;
            }
            // col 1
            {
                float xr = wA[1].w + wA[1].x * x0 + wA[1].y * x1 + wA[1].z * x2;
                float xz = wB[1].w + wB[1].x * x0 + wB[1].y * x1 + wB[1].z * x2;
                float xn = wN1.w + wN1.x * x0 + wN1.y * x1 + wN1.z * x2;
                float r = sigf(xr + pr1 + bhr[1]);
                float z = sigf(xz + pz1 + bhz[1]);
                float n = tanhf_(xn + r * (pn1 + bhn[1]));
                float h = n + z * (hp[mi][1] - n);
                if (addn) h += noise[(bb * 16 + bl) * HSZ + ib * 32 + lc0 + 1];
                hp[mi][1] = h; hnew[mi][1] = h;
            }
            // split-h store (2 cols packed per buffer)
            {
                __nv_bfloat16 h0 = __float2bfloat16(hnew[mi][0]);
                __nv_bfloat16 h1 = __float2bfloat16(hnew[mi][1]);
                __nv_bfloat16 l0 = __float2bfloat16(hnew[mi][0] - __bfloat162float(h0));
                __nv_bfloat16 l1 = __float2bfloat16(hnew[mi][1] - __bfloat162float(h1));
                int off = (bb * 16 + bl) * HSZ + ib * 32 + lc0;
                *(uint32_t*)(&g_hbf[0][(t + 1) & 1][off]) =
                    (uint32_t)__bfloat16_as_ushort(h0)
                    | ((uint32_t)__bfloat16_as_ushort(h1) << 16);
                *(uint32_t*)(&g_hbf[1][(t + 1) & 1][off]) =
                    (uint32_t)__bfloat16_as_ushort(l0)
                    | ((uint32_t)__bfloat16_as_ushort(l1) << 16);
            }
        }

        // fused FC head partial (decoder): per-warp, 2 shfls over q
        if (!enc) {
            #pragma unroll
            for (int mi = 0; mi < 2; ++mi) {
                float y0 = hnew[mi][0] * wfc_s[lc0] + hnew[mi][1] * wfc_s[lc0 + 1];
                float y1 = hnew[mi][0] * wfc_s[32 + lc0] + hnew[mi][1] * wfc_s[32 + lc0 + 1];
                float y2 = hnew[mi][0] * wfc_s[64 + lc0] + hnew[mi][1] * wfc_s[64 + lc0 + 1];
                y0 += __shfl_xor_sync(0xffffffffu, y0, 1);
                y0 += __shfl_xor_sync(0xffffffffu, y0, 2);
                y1 += __shfl_xor_sync(0xffffffffu, y1, 1);
                y1 += __shfl_xor_sync(0xffffffffu, y1, 2);
                y2 += __shfl_xor_sync(0xffffffffu, y2, 1);
                y2 += __shfl_xor_sync(0xffffffffu, y2, 2);
                if (q == 0)
                    g_yp[t & 1][blockIdx.x][w][rr + mi * 8] =
                        make_float4(y0, y1, y2, 0.f);
            }
        }

        // publish production index t+1
        __syncthreads();
        if (tid == 0) arrive(cnt);
    }

    // final head reduction for tstep = 255 (partials at t=511, buf par=1)
    if (tid == 0) wait_ge(cnt, 8u * 513u);
    __syncthreads();
    if (tid < 2) {
        int bl = ib * 2 + tid;
        float s0 = bfc[0], s1 = bfc[1], s2 = bfc[2];
        #pragma unroll
        for (int p = 0; p < 8; ++p)
            #pragma unroll
            for (int ww = 0; ww < 4; ++ww) {
                float4 v = g_yp[1][bb * 8 + p][ww][bl];
                s0 += v.x; s1 += v.y; s2 += v.z;
            }
        float* po = &out[((bb * 16 + bl) * TSZ + (TSZ - 1)) * 3];
        po[0] = s0; po[1] = s1; po[2] = s2;
    }
    __syncthreads();
    if (tid == 0) arrive(cnt);

    // counter reset for graph replay
    if (ib == 0 && tid == 0) {
        wait_ge(cnt, 8u * 514u);
        asm volatile("st.release.gpu.u32 [%0], %1;" :: "l"(cnt), "r"(0u) : "memory");
    }
}

extern "C" void kernel_launch(void* const* d_in, const int* in_sizes, int n_in,
                              void* d_out, int out_size) {
    const float* X_p   = (const float*)d_in[0];
    const float* X_f   = (const float*)d_in[1];
    const float* noise = (const float*)d_in[2];
    const float* Wih_e = (const float*)d_in[3];
    const float* Whh_e = (const float*)d_in[4];
    const float* bih_e = (const float*)d_in[5];
    const float* bhh_e = (const float*)d_in[6];
    const float* Wih_d = (const float*)d_in[7];
    const float* Whh_d = (const float*)d_in[8];
    const float* bih_d = (const float*)d_in[9];
    const float* bhh_d = (const float*)d_in[10];
    const float* Wfc   = (const float*)d_in[11];
    const float* bfc   = (const float*)d_in[12];
    float* out = (float*)d_out;

    cudaFuncSetAttribute(netg_mma, cudaFuncAttributeMaxDynamicSharedMemorySize,
                         SMEM_BYTES);
    netg_mma<<<NCTA, NTHR, SMEM_BYTES>>>(
        X_p, X_f, noise, Wih_e, Whh_e, bih_e, bhh_e,
        Wih_d, Whh_d, bih_d, bhh_d, Wfc, bfc, out);
}

// round 16
// speedup vs baseline: 2.4734x; 1.0186x over previous
#include <cuda_runtime.h>
#include <cuda_bf16.h>
#include <cstdint>

// NetG: encoder GRU -> +noise -> decoder GRU -> FC head.
// mma.sync.m16n8k16 bf16 x3-split GEMM, R10 counter sync, R15 register-local
// epilogue (full-K per warp, gate-interleaved B, no CBUF). R16: early arrive
// right after h-stores (head-partial shfl+store moved off the inter-CTA
// critical path, 4-deep yp parity, reduce at t-2), x_t staged pre-poll,
// head-reduce overlapped with staging LDGs.

#define TSZ 256
#define HSZ 256
#define BSZ 512
#define NCTA 256
#define NTHR 128

// smem byte offsets
#define A_HI 0                // 16 x 512B swizzled bf16 (Ah)
#define A_LO 8192             // Al
#define WIHB 16384            // 96 x float4 {w0,w1,w2,bih}  (g*32+c)
#define BHHO 17920            // 96 floats bhh
#define WFCO 18304            // 96 floats wfc (d*32+c)
#define XS   18688            // 16*3 floats x_t
#define SMEM_BYTES 18880

__device__ __nv_bfloat16 g_hbf[2][2][BSZ * HSZ];  // [hi/lo][buf][b*256+j]
__device__ float4 g_yp[4][NCTA][4][16];           // head partials, 4-deep parity
__device__ unsigned g_cnt[32][32];                // [bb][pad] monotonic counter

__device__ __forceinline__ uint32_t smem_u32(const void* p) {
    uint32_t a;
    asm("{ .reg .u64 t; cvta.to.shared.u64 t, %1; cvt.u32.u64 %0, t; }"
        : "=r"(a) : "l"(p));
    return a;
}
__device__ __forceinline__ void ldm4(uint32_t* r, uint32_t addr) {
    asm volatile("ldmatrix.sync.aligned.m8n8.x4.shared.b16 {%0,%1,%2,%3}, [%4];"
        : "=r"(r[0]), "=r"(r[1]), "=r"(r[2]), "=r"(r[3]) : "r"(addr));
}
__device__ __forceinline__ void mma16816(float* c, const uint32_t* a,
                                         uint32_t b0, uint32_t b1) {
    asm volatile(
        "mma.sync.aligned.m16n8k16.row.col.f32.bf16.bf16.f32 "
        "{%0,%1,%2,%3}, {%4,%5,%6,%7}, {%8,%9}, {%0,%1,%2,%3};"
        : "+f"(c[0]), "+f"(c[1]), "+f"(c[2]), "+f"(c[3])
        : "r"(a[0]), "r"(a[1]), "r"(a[2]), "r"(a[3]), "r"(b0), "r"(b1));
}
__device__ __forceinline__ void arrive(unsigned* cnt) {
    asm volatile("red.add.release.gpu.u32 [%0], 1;" :: "l"(cnt) : "memory");
}
__device__ __forceinline__ void wait_ge(const unsigned* cnt, unsigned target) {
    unsigned v;
    do {
        asm volatile("ld.acquire.gpu.u32 %0, [%1];" : "=r"(v) : "l"(cnt) : "memory");
    } while ((int)(v - target) < 0);
}
__device__ __forceinline__ float sigf(float x) {
    return __fdividef(1.0f, 1.0f + __expf(-x));
}
__device__ __forceinline__ float tanhf_(float x) {
    return 1.0f - __fdividef(2.0f, __expf(2.0f * x) + 1.0f);
}

// Gate-interleaved B fragments: warp w covers 24 N-rows (3 tiles), full K.
// Fragment (nt, nr=lane>>2) maps to (col, gate) so C-fragment threads own
// complete r/z/n triples for cols 2q, 2q+1 (q = lane&3).
__device__ __forceinline__ void stage_Bregs(
    const float* __restrict__ W, uint32_t Bh[3][16][2], uint32_t Bl[3][16][2],
    int ib, int w, int lane)
{
    const int nr = lane >> 2, kc = (lane & 3) * 2;
    const int odd = nr & 1, q2 = nr >> 1;
    #pragma unroll
    for (int nt = 0; nt < 3; ++nt) {
        int idx = nt * 2 + odd;
        int hi3 = (idx >= 3);
        int cl = q2 * 2 + hi3;
        int g = idx - 3 * hi3;
        const float* row = W + (g * HSZ + ib * 32 + w * 8 + cl) * HSZ;
        #pragma unroll
        for (int kt = 0; kt < 16; ++kt) {
            #pragma unroll
            for (int rg = 0; rg < 2; ++rg) {
                int kk = kt * 16 + rg * 8 + kc;
                float2 wv = *(const float2*)(row + kk);
                __nv_bfloat16 h0 = __float2bfloat16(wv.x);
                __nv_bfloat16 h1 = __float2bfloat16(wv.y);
                __nv_bfloat16 l0 = __float2bfloat16(wv.x - __bfloat162float(h0));
                __nv_bfloat16 l1 = __float2bfloat16(wv.y - __bfloat162float(h1));
                Bh[nt][kt][rg] = (uint32_t)__bfloat16_as_ushort(h0)
                               | ((uint32_t)__bfloat16_as_ushort(h1) << 16);
                Bl[nt][kt][rg] = (uint32_t)__bfloat16_as_ushort(l0)
                               | ((uint32_t)__bfloat16_as_ushort(l1) << 16);
            }
        }
    }
}

extern "C" __global__ void __launch_bounds__(NTHR, 2)
netg_mma(const float* __restrict__ X_p, const float* __restrict__ X_f,
         const float* __restrict__ noise,
         const float* __restrict__ Wih_e, const float* __restrict__ Whh_e,
         const float* __restrict__ bih_e, const float* __restrict__ bhh_e,
         const float* __restrict__ Wih_d, const float* __restrict__ Whh_d,
         const float* __restrict__ bih_d, const float* __restrict__ bhh_d,
         const float* __restrict__ Wfc,   const float* __restrict__ bfc,
         float* __restrict__ out)
{
    extern __shared__ char smc[];
    const uint32_t smb = smem_u32(smc);
    const int tid = threadIdx.x, lane = tid & 31, w = tid >> 5;
    const int bb = blockIdx.x >> 3, ib = blockIdx.x & 7;
    const int rr = lane >> 2, q = lane & 3;

    float4* wihb_s = (float4*)(smc + WIHB);
    float*  bhh_s  = (float*)(smc + BHHO);
    float*  wfc_s  = (float*)(smc + WFCO);
    float*  x_s    = (float*)(smc + XS);
    unsigned* cnt  = &g_cnt[bb][0];

    // ---- weights into registers / params into SMEM (encoder phase) ----
    uint32_t Bh[3][16][2], Bl[3][16][2];
    stage_Bregs(Whh_e, Bh, Bl, ib, w, lane);
    if (tid < 96) {
        int g = tid >> 5, c = tid & 31;
        int row = g * HSZ + ib * 32 + c;
        wihb_s[tid] = make_float4(Wih_e[row * 3], Wih_e[row * 3 + 1],
                                  Wih_e[row * 3 + 2], bih_e[row]);
        bhh_s[tid] = bhh_e[row];
        wfc_s[tid] = Wfc[g * HSZ + ib * 32 + c];
    }

    // this thread's epilogue ownership: batches rr, rr+8; cols lc0, lc0+1
    const int lc0 = w * 8 + q * 2;
    const int bg0 = bb * 16 + rr, bg1 = bg0 + 8;

    // zero h buffer 0 (production index 0)
    {
        uint32_t z = 0;
        #pragma unroll
        for (int p = 0; p < 2; ++p) {
            *(uint32_t*)(&g_hbf[p][0][bg0 * HSZ + ib * 32 + lc0]) = z;
            *(uint32_t*)(&g_hbf[p][0][bg1 * HSZ + ib * 32 + lc0]) = z;
        }
    }
    float hp[2][2] = {{0.f, 0.f}, {0.f, 0.f}};   // [m(0:rr,1:rr+8)][col]
    __syncthreads();
    if (tid == 0) arrive(cnt);   // init arrival: buffer 0 published

    // ldmatrix per-lane address bases (m16 x k16 via x4)
    const int lgrp = lane >> 3, lrow = lane & 7;
    const int r0 = ((lgrp & 1) << 3) + lrow;
    const int segoff = lgrp >> 1;
    const uint32_t rbh0 = smb + A_HI + r0 * 512;
    const uint32_t rbl0 = smb + A_LO + r0 * 512;

    for (int t = 0; t < 2 * TSZ; ++t) {
        const bool enc = t < TSZ;
        const int tt = enc ? t : t - TSZ;

        // stage x_t into SMEM BEFORE the poll (no flag dependence; previous
        // readers finished before last step's h-store sync)
        if (tid < 48) {
            int bl = tid / 3, d = tid - bl * 3;
            float v = 0.f;
            if (enc)          v = X_p[(bb * 16 + bl) * (TSZ * 3) + tt * 3 + d];
            else if (tt > 0)  v = X_f[(bb * 16 + bl) * (TSZ * 3) + (tt - 1) * 3 + d];
            x_s[bl * 3 + d] = v;
        }

        // ---- entry barrier: all 8 producers of this group reached index t ----
        if (tid == 0) wait_ge(cnt, 8u * (unsigned)(t + 1));
        __syncthreads();

        if (t == TSZ) {   // switch to decoder weights
            stage_Bregs(Whh_d, Bh, Bl, ib, w, lane);
            if (tid < 96) {
                int g = tid >> 5, c = tid & 31;
                int row = g * HSZ + ib * 32 + c;
                wihb_s[tid] = make_float4(Wih_d[row * 3], Wih_d[row * 3 + 1],
                                          Wih_d[row * 3 + 2], bih_d[row]);
                bhh_s[tid] = bhh_d[row];
            }
        }

        // ---- stage A (split h): 1024 16B-chunks, 8 per thread ----
        {
            const __nv_bfloat16* s_hi = g_hbf[0][t & 1] + bb * 16 * HSZ;
            const __nv_bfloat16* s_lo = g_hbf[1][t & 1] + bb * 16 * HSZ;
            #pragma unroll
            for (int i2 = 0; i2 < 8; ++i2) {
                int idx = tid + i2 * NTHR;
                int p = idx >> 9, rem = idx & 511;
                int mm = rem >> 5, s = rem & 31;
                const __nv_bfloat16* src = (p ? s_lo : s_hi) + mm * HSZ + s * 8;
                uint4 v = *(const uint4*)src;
                char* db = smc + (p ? A_LO : A_HI);
                *(uint4*)(db + mm * 512 + ((s ^ (mm & 7)) << 4)) = v;
            }
        }

        // distributed head reduce for decoder tstep tt-2 (yp slot (t-2)&3;
        // guarded by the arrive set this step's poll just consumed)
        if (t >= TSZ + 2 && tid < 2) {
            int bl = ib * 2 + tid;
            float s0 = bfc[0], s1 = bfc[1], s2 = bfc[2];
            #pragma unroll
            for (int p = 0; p < 8; ++p)
                #pragma unroll
                for (int ww = 0; ww < 4; ++ww) {
                    float4 v = g_yp[(t - 2) & 3][bb * 8 + p][ww][bl];
                    s0 += v.x; s1 += v.y; s2 += v.z;
                }
            float* po = &out[((bb * 16 + bl) * TSZ + (tt - 2)) * 3];
            po[0] = s0; po[1] = s1; po[2] = s2;
        }
        __syncthreads();

        // ---- tensor-core GEMM: full K per warp, C complete in registers ----
        float c[3][4];
        #pragma unroll
        for (int nt = 0; nt < 3; ++nt)
            #pragma unroll
            for (int d2 = 0; d2 < 4; ++d2) c[nt][d2] = 0.f;

        #pragma unroll
        for (int kt = 0; kt < 16; ++kt) {
            int seg = kt * 2 + segoff;
            uint32_t so = (uint32_t)((seg ^ lrow) << 4);
            uint32_t ah[4], al[4];
            ldm4(ah, rbh0 + so);
            ldm4(al, rbl0 + so);
            #pragma unroll
            for (int nt = 0; nt < 3; ++nt) {
                mma16816(c[nt], ah, Bh[nt][kt][0], Bh[nt][kt][1]);
                mma16816(c[nt], al, Bh[nt][kt][0], Bh[nt][kt][1]);
                mma16816(c[nt], ah, Bl[nt][kt][0], Bl[nt][kt][1]);
            }
        }

        // ---- register-local epilogue: gates, h update, h store ----
        //  col lc0:   r=c[0][f0], z=c[0][f1], n=c[1][f0]
        //  col lc0+1: r=c[1][f1], z=c[2][f0], n=c[2][f1]
        const bool addn = (t == TSZ - 1);
        float4 wA[2], wB[2];
        float bhr[2], bhz[2], bhn[2];
        #pragma unroll
        for (int cc = 0; cc < 2; ++cc) {
            int lc = lc0 + cc;
            wA[cc] = wihb_s[lc];
            wB[cc] = wihb_s[32 + lc];
            bhr[cc] = bhh_s[lc];
            bhz[cc] = bhh_s[32 + lc];
            bhn[cc] = bhh_s[64 + lc];
        }
        float4 wN0 = wihb_s[64 + lc0], wN1 = wihb_s[64 + lc0 + 1];

        float hnew[2][2];
        #pragma unroll
        for (int mi = 0; mi < 2; ++mi) {
            int bl = rr + mi * 8;
            int f0 = mi * 2, f1 = mi * 2 + 1;
            float x0 = x_s[bl * 3], x1 = x_s[bl * 3 + 1], x2 = x_s[bl * 3 + 2];
            float pr0 = c[0][f0], pz0 = c[0][f1], pn0 = c[1][f0];
            float pr1 = c[1][f1], pz1 = c[2][f0], pn1 = c[2][f1];
            {
                float xr = wA[0].w + wA[0].x * x0 + wA[0].y * x1 + wA[0].z * x2;
                float xz = wB[0].w + wB[0].x * x0 + wB[0].y * x1 + wB[0].z * x2;
                float xn = wN0.w + wN0.x * x0 + wN0.y * x1 + wN0.z * x2;
                float r = sigf(xr + pr0 + bhr[0]);
                float z = sigf(xz + pz0 + bhz[0]);
                float n = tanhf_(xn + r * (pn0 + bhn[0]));
                float h = n + z * (hp[mi][0] - n);
                if (addn) h += noise[(bb * 16 + bl) * HSZ + ib * 32 + lc0];
                hp[mi][0] = h; hnew[mi][0] = h;
            }
            {
                float xr = wA[1].w + wA[1].x * x0 + wA[1].y * x1 + wA[1].z * x2;
                float xz = wB[1].w + wB[1].x * x0 + wB[1].y * x1 + wB[1].z * x2;
                float xn = wN1.w + wN1.x * x0 + wN1.y * x1 + wN1.z * x2;
                float r = sigf(xr + pr1 + bhr[1]);
                float z = sigf(xz + pz1 + bhz[1]);
                float n = tanhf_(xn + r * (pn1 + bhn[1]));
                float h = n + z * (hp[mi][1] - n);
                if (addn) h += noise[(bb * 16 + bl) * HSZ + ib * 32 + lc0 + 1];
                hp[mi][1] = h; hnew[mi][1] = h;
            }
            // split-h store (2 cols packed per buffer)
            {
                __nv_bfloat16 h0 = __float2bfloat16(hnew[mi][0]);
                __nv_bfloat16 h1 = __float2bfloat16(hnew[mi][1]);
                __nv_bfloat16 l0 = __float2bfloat16(hnew[mi][0] - __bfloat162float(h0));
                __nv_bfloat16 l1 = __float2bfloat16(hnew[mi][1] - __bfloat162float(h1));
                int off = (bb * 16 + bl) * HSZ + ib * 32 + lc0;
                *(uint32_t*)(&g_hbf[0][(t + 1) & 1][off]) =
                    (uint32_t)__bfloat16_as_ushort(h0)
                    | ((uint32_t)__bfloat16_as_ushort(h1) << 16);
                *(uint32_t*)(&g_hbf[1][(t + 1) & 1][off]) =
                    (uint32_t)__bfloat16_as_ushort(l0)
                    | ((uint32_t)__bfloat16_as_ushort(l1) << 16);
            }
        }

        // EARLY publish: h stores complete -> arrive now; head-partial work
        // happens after, off the inter-CTA critical path. Final step arrives
        // late so the post-loop wait also covers its yp write.
        __syncthreads();
        if (tid == 0 && t != 2 * TSZ - 1) arrive(cnt);

        // fused FC head partial (decoder): per-warp, 2 shfls over q
        if (!enc) {
            #pragma unroll
            for (int mi = 0; mi < 2; ++mi) {
                float y0 = hnew[mi][0] * wfc_s[lc0] + hnew[mi][1] * wfc_s[lc0 + 1];
                float y1 = hnew[mi][0] * wfc_s[32 + lc0] + hnew[mi][1] * wfc_s[32 + lc0 + 1];
                float y2 = hnew[mi][0] * wfc_s[64 + lc0] + hnew[mi][1] * wfc_s[64 + lc0 + 1];
                y0 += __shfl_xor_sync(0xffffffffu, y0, 1);
                y0 += __shfl_xor_sync(0xffffffffu, y0, 2);
                y1 += __shfl_xor_sync(0xffffffffu, y1, 1);
                y1 += __shfl_xor_sync(0xffffffffu, y1, 2);
                y2 += __shfl_xor_sync(0xffffffffu, y2, 1);
                y2 += __shfl_xor_sync(0xffffffffu, y2, 2);
                if (q == 0)
                    g_yp[t & 3][blockIdx.x][w][rr + mi * 8] =
                        make_float4(y0, y1, y2, 0.f);
            }
        }
        if (t == 2 * TSZ - 1) {   // final step: late arrive covers yp write
            __syncthreads();
            if (tid == 0) arrive(cnt);
        }
    }

    // post-loop: reduce decoder tsteps 254 (yp slot 2) and 255 (slot 3)
    if (tid == 0) wait_ge(cnt, 8u * 513u);
    __syncthreads();
    if (tid < 4) {
        int sel = tid >> 1;                 // 0 -> tstep 254, 1 -> tstep 255
        int bl = ib * 2 + (tid & 1);
        int slot = 2 + sel;
        float s0 = bfc[0], s1 = bfc[1], s2 = bfc[2];
        #pragma unroll
        for (int p = 0; p < 8; ++p)
            #pragma unroll
            for (int ww = 0; ww < 4; ++ww) {
                float4 v = g_yp[slot][bb * 8 + p][ww][bl];
                s0 += v.x; s1 += v.y; s2 += v.z;
            }
        float* po = &out[((bb * 16 + bl) * TSZ + 254 + sel) * 3];
        po[0] = s0; po[1] = s1; po[2] = s2;
    }
    __syncthreads();
    if (tid == 0) arrive(cnt);

    // counter reset for graph replay
    if (ib == 0 && tid == 0) {
        wait_ge(cnt, 8u * 514u);
        asm volatile("st.release.gpu.u32 [%0], %1;" :: "l"(cnt), "r"(0u) : "memory");
    }
}

extern "C" void kernel_launch(void* const* d_in, const int* in_sizes, int n_in,
                              void* d_out, int out_size) {
    const float* X_p   = (const float*)d_in[0];
    const float* X_f   = (const float*)d_in[1];
    const float* noise = (const float*)d_in[2];
    const float* Wih_e = (const float*)d_in[3];
    const float* Whh_e = (const float*)d_in[4];
    const float* bih_e = (const float*)d_in[5];
    const float* bhh_e = (const float*)d_in[6];
    const float* Wih_d = (const float*)d_in[7];
    const float* Whh_d = (const float*)d_in[8];
    const float* bih_d = (const float*)d_in[9];
    const float* bhh_d = (const float*)d_in[10];
    const float* Wfc   = (const float*)d_in[11];
    const float* bfc   = (const float*)d_in[12];
    float* out = (float*)d_out;

    cudaFuncSetAttribute(netg_mma, cudaFuncAttributeMaxDynamicSharedMemorySize,
                         SMEM_BYTES);
    netg_mma<<<NCTA, NTHR, SMEM_BYTES>>>(
        X_p, X_f, noise, Wih_e, Whh_e, bih_e, bhh_e,
        Wih_d, Whh_d, bih_d, bhh_d, Wfc, bfc, out);
}